// round 2
// baseline (speedup 1.0000x reference)
#include <cuda_runtime.h>
#include <cuda_bf16.h>
#include <math.h>

// Problem constants
#define S 2048
#define D 2048
#define H 16
#define HD 128
#define FFI 8192
#define EPS 1e-5f

// ---------------------------------------------------------------------------
// Scratch (static device globals; no allocation anywhere)
// ---------------------------------------------------------------------------
__device__ float g_nx[S * D];        // normed activations (reused twice)
__device__ float g_q[S * D];
__device__ float g_k[S * D];
__device__ float g_v[S * D];
__device__ float g_ao[S * D];        // attention output (pre-proj)
__device__ float g_x1[S * D];        // x + attn_out @ wo
__device__ float g_h1[S * FFI];      // nx @ w1 (then silu*h3 in place)
__device__ float g_h3[S * FFI];      // nx @ w3

// ---------------------------------------------------------------------------
// Packed fp32x2 helpers (Blackwell FFMA2 — only reachable via PTX)
// ---------------------------------------------------------------------------
__device__ __forceinline__ unsigned long long pack2(float x, float y) {
    unsigned long long r;
    asm("mov.b64 %0, {%1, %2};" : "=l"(r) : "f"(x), "f"(y));
    return r;
}
__device__ __forceinline__ void ffma2(unsigned long long& d,
                                      unsigned long long a,
                                      unsigned long long b) {
    asm("fma.rn.f32x2 %0, %1, %2, %0;" : "+l"(d) : "l"(a), "l"(b));
}
__device__ __forceinline__ float2 unpack2(unsigned long long v) {
    float2 r;
    asm("mov.b64 {%0, %1}, %2;" : "=f"(r.x), "=f"(r.y) : "l"(v));
    return r;
}

// ---------------------------------------------------------------------------
// RMSNorm: one block per row, 256 threads
// ---------------------------------------------------------------------------
__global__ __launch_bounds__(256) void rmsnorm_kernel(
    const float* __restrict__ X, const float* __restrict__ W,
    float* __restrict__ Y)
{
    int row = blockIdx.x;
    const float4* x4 = (const float4*)(X + (size_t)row * D);
    const float4* w4 = (const float4*)W;
    float4* y4 = (float4*)(Y + (size_t)row * D);

    float ss = 0.f;
    #pragma unroll 2
    for (int i = threadIdx.x; i < D / 4; i += 256) {
        float4 v = x4[i];
        ss += v.x * v.x + v.y * v.y + v.z * v.z + v.w * v.w;
    }
    #pragma unroll
    for (int o = 16; o; o >>= 1) ss += __shfl_xor_sync(0xffffffffu, ss, o);

    __shared__ float red[8];
    __shared__ float s_inv;
    if ((threadIdx.x & 31) == 0) red[threadIdx.x >> 5] = ss;
    __syncthreads();
    if (threadIdx.x == 0) {
        float t = red[0] + red[1] + red[2] + red[3] +
                  red[4] + red[5] + red[6] + red[7];
        s_inv = rsqrtf(t / (float)D + EPS);
    }
    __syncthreads();
    float inv = s_inv;
    #pragma unroll 2
    for (int i = threadIdx.x; i < D / 4; i += 256) {
        float4 v = x4[i];
        float4 w = w4[i];
        float4 y;
        y.x = w.x * (v.x * inv);
        y.y = w.y * (v.y * inv);
        y.z = w.z * (v.z * inv);
        y.w = w.w * (v.w * inv);
        y4[i] = y;
    }
}

// ---------------------------------------------------------------------------
// SGEMM: C[M,N] = A[M,K] @ B[K,N] (+ optional residual R[M,N])
// 128x128 tile, BK=8, 256 threads, 8x8 per-thread microtile, FFMA2 inner loop
// M,N,K all multiples of 128 here -> no bounds checks
// ---------------------------------------------------------------------------
__global__ __launch_bounds__(256) void sgemm_kernel(
    const float* __restrict__ A, const float* __restrict__ B,
    const float* __restrict__ R, float* __restrict__ C,
    int M, int N, int K)
{
    constexpr int BM = 128, BN = 128, BK = 8, TM = 8;
    __shared__ float As[BK][BM];
    __shared__ float Bs[BK][BN];

    int tid = threadIdx.x;
    int tx = tid & 15;        // 0..15 -> N direction
    int ty = tid >> 4;        // 0..15 -> M direction

    const float* Ab = A + (size_t)blockIdx.y * BM * K;
    const float* Bb = B + (size_t)blockIdx.x * BN;

    int aRow = tid >> 1;           // 0..127
    int aCol = (tid & 1) * 4;      // 0 or 4
    int bRow = tid >> 5;           // 0..7
    int bCol = (tid & 31) * 4;     // 0..124

    unsigned long long acc[TM][4];
    #pragma unroll
    for (int i = 0; i < TM; i++)
        #pragma unroll
        for (int j = 0; j < 4; j++) acc[i][j] = 0ULL;

    for (int k0 = 0; k0 < K; k0 += BK) {
        float4 a4 = *(const float4*)(Ab + (size_t)aRow * K + k0 + aCol);
        As[aCol + 0][aRow] = a4.x;
        As[aCol + 1][aRow] = a4.y;
        As[aCol + 2][aRow] = a4.z;
        As[aCol + 3][aRow] = a4.w;
        *(float4*)(&Bs[bRow][bCol]) =
            *(const float4*)(Bb + (size_t)(k0 + bRow) * N + bCol);
        __syncthreads();

        #pragma unroll
        for (int k = 0; k < BK; k++) {
            unsigned long long ar2[TM], br2[4];
            #pragma unroll
            for (int i = 0; i < TM; i++) {
                float a = As[k][ty * TM + i];
                ar2[i] = pack2(a, a);
            }
            #pragma unroll
            for (int j = 0; j < 4; j++)
                br2[j] = *(const unsigned long long*)(&Bs[k][tx * 8 + 2 * j]);
            #pragma unroll
            for (int i = 0; i < TM; i++)
                #pragma unroll
                for (int j = 0; j < 4; j++)
                    ffma2(acc[i][j], ar2[i], br2[j]);
        }
        __syncthreads();
    }

    // epilogue
    #pragma unroll
    for (int i = 0; i < TM; i++) {
        size_t row = (size_t)blockIdx.y * BM + ty * TM + i;
        #pragma unroll
        for (int jj = 0; jj < 2; jj++) {
            size_t col = (size_t)blockIdx.x * BN + tx * 8 + jj * 4;
            float2 p0 = unpack2(acc[i][2 * jj + 0]);
            float2 p1 = unpack2(acc[i][2 * jj + 1]);
            float4 r = make_float4(p0.x, p0.y, p1.x, p1.y);
            if (R) {
                float4 rv = *(const float4*)(R + row * (size_t)N + col);
                r.x += rv.x; r.y += rv.y; r.z += rv.z; r.w += rv.w;
            }
            *(float4*)(C + row * (size_t)N + col) = r;
        }
    }
}

// ---------------------------------------------------------------------------
// RoPE (duplicated-half convention): in-place on Q and K
// one thread per (s, h, d<64) pair
// ---------------------------------------------------------------------------
__global__ __launch_bounds__(256) void rope_kernel(
    float* __restrict__ Q, float* __restrict__ Kp,
    const float* __restrict__ cosb, const float* __restrict__ sinb)
{
    int idx = blockIdx.x * blockDim.x + threadIdx.x;  // S*H*64
    int d  = idx & 63;
    int h  = (idx >> 6) & (H - 1);
    int s  = idx >> 10;
    size_t base = (size_t)s * D + (size_t)h * HD;
    float c  = cosb[s * HD + d];   // cos[d] == cos[d+64]
    float sn = sinb[s * HD + d];

    float q0 = Q[base + d], q1 = Q[base + d + 64];
    Q[base + d]      = q0 * c - q1 * sn;
    Q[base + d + 64] = q1 * c + q0 * sn;

    float k0 = Kp[base + d], k1 = Kp[base + d + 64];
    Kp[base + d]      = k0 * c - k1 * sn;
    Kp[base + d + 64] = k1 * c + k0 * sn;
}

// ---------------------------------------------------------------------------
// Causal attention: one warp per (head, query row), online softmax.
// Lane holds 4 contiguous dims of q / acc. exp(-1e9) underflow == hard cutoff.
// ---------------------------------------------------------------------------
__global__ __launch_bounds__(256) void attn_kernel(
    const float* __restrict__ Q, const float* __restrict__ K,
    const float* __restrict__ V, float* __restrict__ O)
{
    int warp = threadIdx.x >> 5;
    int lane = threadIdx.x & 31;
    int qr = blockIdx.x * 8 + warp;
    int h  = blockIdx.y;
    size_t hoff = (size_t)h * HD + (size_t)lane * 4;

    float4 q4 = *(const float4*)(Q + (size_t)qr * D + hoff);
    float m = -1e30f, l = 0.f;
    float ax = 0.f, ay = 0.f, az = 0.f, aw = 0.f;
    const float scale = 0.08838834764831845f;  // 1/sqrt(128)

    const float* kp = K + hoff;
    const float* vp = V + hoff;

    for (int kv = 0; kv <= qr; kv++) {
        float4 k4 = *(const float4*)(kp + (size_t)kv * D);
        float s = q4.x * k4.x + q4.y * k4.y + q4.z * k4.z + q4.w * k4.w;
        #pragma unroll
        for (int o = 16; o; o >>= 1) s += __shfl_xor_sync(0xffffffffu, s, o);
        s *= scale;
        float nm = fmaxf(m, s);
        float f = __expf(m - nm);   // 0 on first iter
        float p = __expf(s - nm);
        float4 v4 = *(const float4*)(vp + (size_t)kv * D);
        l = l * f + p;
        ax = ax * f + p * v4.x;
        ay = ay * f + p * v4.y;
        az = az * f + p * v4.z;
        aw = aw * f + p * v4.w;
        m = nm;
    }
    float rl = 1.f / l;
    float4 o4 = make_float4(ax * rl, ay * rl, az * rl, aw * rl);
    *(float4*)(O + (size_t)qr * D + hoff) = o4;
}

// ---------------------------------------------------------------------------
// SiLU(h1) * h3 -> h1, vectorized
// ---------------------------------------------------------------------------
__global__ __launch_bounds__(256) void silu_mul_kernel(
    float* __restrict__ H1, const float* __restrict__ H3)
{
    size_t i = (size_t)blockIdx.x * blockDim.x + threadIdx.x;  // over float4s
    float4 a = ((const float4*)H1)[i];
    float4 b = ((const float4*)H3)[i];
    float4 r;
    r.x = (a.x / (1.f + __expf(-a.x))) * b.x;
    r.y = (a.y / (1.f + __expf(-a.y))) * b.y;
    r.z = (a.z / (1.f + __expf(-a.z))) * b.z;
    r.w = (a.w / (1.f + __expf(-a.w))) * b.w;
    ((float4*)H1)[i] = r;
}

// ---------------------------------------------------------------------------
// Launch
// ---------------------------------------------------------------------------
extern "C" void kernel_launch(void* const* d_in, const int* in_sizes, int n_in,
                              void* d_out, int out_size)
{
    const float* x    = (const float*)d_in[0];
    // d_in[1] = attention_mask (pure causal; enforced by loop bound)
    const float* fcos = (const float*)d_in[2];
    const float* fsin = (const float*)d_in[3];
    const float* wq   = (const float*)d_in[4];
    const float* wk   = (const float*)d_in[5];
    const float* wv   = (const float*)d_in[6];
    const float* wo   = (const float*)d_in[7];
    const float* w1   = (const float*)d_in[8];
    const float* w2   = (const float*)d_in[9];
    const float* w3   = (const float*)d_in[10];
    const float* anw  = (const float*)d_in[11];
    const float* fnw  = (const float*)d_in[12];
    float* out = (float*)d_out;

    float *nx, *q, *k, *v, *ao, *x1, *h1, *h3;
    cudaGetSymbolAddress((void**)&nx, g_nx);
    cudaGetSymbolAddress((void**)&q,  g_q);
    cudaGetSymbolAddress((void**)&k,  g_k);
    cudaGetSymbolAddress((void**)&v,  g_v);
    cudaGetSymbolAddress((void**)&ao, g_ao);
    cudaGetSymbolAddress((void**)&x1, g_x1);
    cudaGetSymbolAddress((void**)&h1, g_h1);
    cudaGetSymbolAddress((void**)&h3, g_h3);

    dim3 gDD(D / 128, S / 128);       // (16,16)
    dim3 gDI(FFI / 128, S / 128);     // (64,16)

    // 1) attn rmsnorm
    rmsnorm_kernel<<<S, 256>>>(x, anw, nx);
    // 2) qkv projections
    sgemm_kernel<<<gDD, 256>>>(nx, wq, nullptr, q, S, D, D);
    sgemm_kernel<<<gDD, 256>>>(nx, wk, nullptr, k, S, D, D);
    sgemm_kernel<<<gDD, 256>>>(nx, wv, nullptr, v, S, D, D);
    // 3) rope on q,k
    rope_kernel<<<(S * H * 64) / 256, 256>>>(q, k, fcos, fsin);
    // 4) causal attention
    attn_kernel<<<dim3(S / 8, H), 256>>>(q, k, v, ao);
    // 5) output projection + residual
    sgemm_kernel<<<gDD, 256>>>(ao, wo, x, x1, S, D, D);
    // 6) ffn rmsnorm
    rmsnorm_kernel<<<S, 256>>>(x1, fnw, nx);
    // 7) gate/up projections
    sgemm_kernel<<<gDI, 256>>>(nx, w1, nullptr, h1, S, FFI, D);
    sgemm_kernel<<<gDI, 256>>>(nx, w3, nullptr, h3, S, FFI, D);
    // 8) silu * h3
    silu_mul_kernel<<<(S * (size_t)FFI / 4) / 256, 256>>>(h1, h3);
    // 9) down projection + residual -> out
    sgemm_kernel<<<gDD, 256>>>(h1, w2, x1, out, S, D, FFI);
}

// round 4
// speedup vs baseline: 2.7494x; 2.7494x over previous
#include <cuda_runtime.h>
#include <cuda_bf16.h>
#include <cstdint>
#include <math.h>

#define S 2048
#define D 2048
#define H 16
#define HD 128
#define FFI 8192
#define EPS 1e-5f

// ---------------------------------------------------------------------------
// Static device scratch (no allocations anywhere)
// ---------------------------------------------------------------------------
__device__ float g_q[S * D];
__device__ float g_k[S * D];
__device__ float g_v[S * D];
__device__ float g_ao[S * D];
__device__ float g_x1[S * D];
__device__ float g_h1[S * FFI];
__device__ float g_h3[S * FFI];

__device__ __nv_bfloat16 g_nx_hi[S * D],  g_nx_lo[S * D];
__device__ __nv_bfloat16 g_ao_hi[S * D],  g_ao_lo[S * D];
__device__ __nv_bfloat16 g_g_hi[S * FFI], g_g_lo[S * FFI];

// transposed + split weights: [N, K] bf16
__device__ __nv_bfloat16 g_wqT_hi[D * D],  g_wqT_lo[D * D];
__device__ __nv_bfloat16 g_wkT_hi[D * D],  g_wkT_lo[D * D];
__device__ __nv_bfloat16 g_wvT_hi[D * D],  g_wvT_lo[D * D];
__device__ __nv_bfloat16 g_woT_hi[D * D],  g_woT_lo[D * D];
__device__ __nv_bfloat16 g_w1T_hi[FFI * D], g_w1T_lo[FFI * D];
__device__ __nv_bfloat16 g_w3T_hi[FFI * D], g_w3T_lo[FFI * D];
__device__ __nv_bfloat16 g_w2T_hi[D * FFI], g_w2T_lo[D * FFI];

// ---------------------------------------------------------------------------
// PTX helpers (all baseline sm_80+ features — compile for compute_103)
// ---------------------------------------------------------------------------
__device__ __forceinline__ uint32_t smem_u32(const void* p) {
    uint32_t a;
    asm("{ .reg .u64 t; cvta.to.shared.u64 t, %1; cvt.u32.u64 %0, t; }"
        : "=r"(a) : "l"(p));
    return a;
}

#define CP_ASYNC16(dst, src) \
    asm volatile("cp.async.cg.shared.global [%0], [%1], 16;" \
                 :: "r"(dst), "l"(src) : "memory")
#define CP_COMMIT() asm volatile("cp.async.commit_group;" ::: "memory")
#define CP_WAIT(n)  asm volatile("cp.async.wait_group %0;" :: "n"(n) : "memory")

#define LDSM_X4(r, addr) \
    asm volatile("ldmatrix.sync.aligned.m8n8.x4.shared.b16 {%0,%1,%2,%3}, [%4];" \
        : "=r"((r)[0]), "=r"((r)[1]), "=r"((r)[2]), "=r"((r)[3]) : "r"(addr))

#define MMA_BF16(c, a, b0, b1) \
    asm volatile("mma.sync.aligned.m16n8k16.row.col.f32.bf16.bf16.f32 " \
        "{%0,%1,%2,%3}, {%4,%5,%6,%7}, {%8,%9}, {%0,%1,%2,%3};" \
        : "+f"((c)[0]), "+f"((c)[1]), "+f"((c)[2]), "+f"((c)[3]) \
        : "r"((a)[0]), "r"((a)[1]), "r"((a)[2]), "r"((a)[3]), "r"(b0), "r"(b1))

// ---------------------------------------------------------------------------
// fp32 -> bf16 hi/lo split helpers
// ---------------------------------------------------------------------------
__device__ __forceinline__ void split1(float x, __nv_bfloat16& h, __nv_bfloat16& l) {
    h = __float2bfloat16_rn(x);
    l = __float2bfloat16_rn(x - __bfloat162float(h));
}
__device__ __forceinline__ void split_store4(__nv_bfloat16* hi, __nv_bfloat16* lo,
                                             size_t idx, float4 y) {
    __nv_bfloat16 h0, h1, h2, h3, l0, l1, l2, l3;
    split1(y.x, h0, l0); split1(y.y, h1, l1);
    split1(y.z, h2, l2); split1(y.w, h3, l3);
    ushort4 hv = make_ushort4(__bfloat16_as_ushort(h0), __bfloat16_as_ushort(h1),
                              __bfloat16_as_ushort(h2), __bfloat16_as_ushort(h3));
    ushort4 lv = make_ushort4(__bfloat16_as_ushort(l0), __bfloat16_as_ushort(l1),
                              __bfloat16_as_ushort(l2), __bfloat16_as_ushort(l3));
    *reinterpret_cast<ushort4*>(hi + idx) = hv;
    *reinterpret_cast<ushort4*>(lo + idx) = lv;
}

// ---------------------------------------------------------------------------
// Weight transpose + split: in [K,N] fp32 -> out [N,K] bf16 hi/lo
// ---------------------------------------------------------------------------
__global__ __launch_bounds__(256) void transpose_split_kernel(
    const float* __restrict__ in, __nv_bfloat16* __restrict__ ohi,
    __nv_bfloat16* __restrict__ olo, int K, int N)
{
    __shared__ float t[32][33];
    int n0 = blockIdx.x * 32, k0 = blockIdx.y * 32;
    int tx = threadIdx.x, ty = threadIdx.y;  // block (32, 8)
    #pragma unroll
    for (int j = 0; j < 4; j++)
        t[ty + 8 * j][tx] = in[(size_t)(k0 + ty + 8 * j) * N + n0 + tx];
    __syncthreads();
    #pragma unroll
    for (int j = 0; j < 4; j++) {
        float v = t[tx][ty + 8 * j];
        size_t o = (size_t)(n0 + ty + 8 * j) * K + k0 + tx;
        __nv_bfloat16 h, l;
        split1(v, h, l);
        ohi[o] = h; olo[o] = l;
    }
}

// ---------------------------------------------------------------------------
// RMSNorm with split bf16 output
// ---------------------------------------------------------------------------
__global__ __launch_bounds__(256) void rmsnorm_split_kernel(
    const float* __restrict__ X, const float* __restrict__ W,
    __nv_bfloat16* __restrict__ Yhi, __nv_bfloat16* __restrict__ Ylo)
{
    int row = blockIdx.x;
    const float4* x4 = (const float4*)(X + (size_t)row * D);
    const float4* w4 = (const float4*)W;

    float ss = 0.f;
    #pragma unroll 2
    for (int i = threadIdx.x; i < D / 4; i += 256) {
        float4 v = x4[i];
        ss += v.x * v.x + v.y * v.y + v.z * v.z + v.w * v.w;
    }
    #pragma unroll
    for (int o = 16; o; o >>= 1) ss += __shfl_xor_sync(0xffffffffu, ss, o);
    __shared__ float red[8];
    __shared__ float s_inv;
    if ((threadIdx.x & 31) == 0) red[threadIdx.x >> 5] = ss;
    __syncthreads();
    if (threadIdx.x == 0) {
        float t = red[0] + red[1] + red[2] + red[3] + red[4] + red[5] + red[6] + red[7];
        s_inv = rsqrtf(t / (float)D + EPS);
    }
    __syncthreads();
    float inv = s_inv;
    #pragma unroll 2
    for (int i = threadIdx.x; i < D / 4; i += 256) {
        float4 v = x4[i];
        float4 w = w4[i];
        float4 y = make_float4(w.x * (v.x * inv), w.y * (v.y * inv),
                               w.z * (v.z * inv), w.w * (v.w * inv));
        split_store4(Yhi, Ylo, (size_t)row * D + i * 4, y);
    }
}

// ---------------------------------------------------------------------------
// Elementwise split (fp32 -> bf16 hi/lo)
// ---------------------------------------------------------------------------
__global__ __launch_bounds__(256) void split_kernel(
    const float* __restrict__ X, __nv_bfloat16* __restrict__ hi,
    __nv_bfloat16* __restrict__ lo)
{
    size_t i = ((size_t)blockIdx.x * blockDim.x + threadIdx.x) * 4;
    float4 v = *reinterpret_cast<const float4*>(X + i);
    split_store4(hi, lo, i, v);
}

// ---------------------------------------------------------------------------
// SiLU(h1)*h3 with split output
// ---------------------------------------------------------------------------
__global__ __launch_bounds__(256) void silu_mul_split_kernel(
    const float* __restrict__ H1, const float* __restrict__ H3,
    __nv_bfloat16* __restrict__ hi, __nv_bfloat16* __restrict__ lo)
{
    size_t i = ((size_t)blockIdx.x * blockDim.x + threadIdx.x) * 4;
    float4 a = *reinterpret_cast<const float4*>(H1 + i);
    float4 b = *reinterpret_cast<const float4*>(H3 + i);
    float4 r;
    r.x = (a.x / (1.f + __expf(-a.x))) * b.x;
    r.y = (a.y / (1.f + __expf(-a.y))) * b.y;
    r.z = (a.z / (1.f + __expf(-a.z))) * b.z;
    r.w = (a.w / (1.f + __expf(-a.w))) * b.w;
    split_store4(hi, lo, i, r);
}

// ---------------------------------------------------------------------------
// HMMA bf16x3 GEMM: C[M,N] = A[M,K] @ B^T[N,K] (+ optional residual R)
// A = Ahi+Alo, B = Bhi+Blo. 128x128 tile, BK=32, 2-stage cp.async pipeline.
// 256 threads, 8 warps (2x4), warp tile 64x32, fp32 reg accum.
// SMEM rows padded to 40 bf16 (80B) -> conflict-free ldmatrix.
// ---------------------------------------------------------------------------
constexpr int ROWP = 40;                       // padded row, bf16 units
constexpr int TILE_BYTES = 128 * ROWP * 2;     // 10240
constexpr int STAGE_BYTES = 4 * TILE_BYTES;    // 40960 (Ahi,Alo,Bhi,Blo)
constexpr int GEMM_SMEM = 2 * STAGE_BYTES;     // 81920

__global__ __launch_bounds__(256, 2) void gemm3_kernel(
    const __nv_bfloat16* __restrict__ Ahi, const __nv_bfloat16* __restrict__ Alo,
    const __nv_bfloat16* __restrict__ Bhi, const __nv_bfloat16* __restrict__ Blo,
    const float* __restrict__ R, float* __restrict__ C, int N, int K)
{
    extern __shared__ __align__(1024) char smem[];
    const uint32_t sb = smem_u32(smem);
    const int tid = threadIdx.x;
    const int warp = tid >> 5, lane = tid & 31;
    const int wm = warp >> 2, wn = warp & 3;       // warp grid 2 x 4
    const int m0 = blockIdx.y * 128, n0 = blockIdx.x * 128;

    const __nv_bfloat16* src0 = Ahi + (size_t)m0 * K;
    const __nv_bfloat16* src1 = Alo + (size_t)m0 * K;
    const __nv_bfloat16* src2 = Bhi + (size_t)n0 * K;
    const __nv_bfloat16* src3 = Blo + (size_t)n0 * K;

    // per-thread load coords (2 x 16B chunks per tile)
    const int r0 = tid >> 2, cc = (tid & 3);       // rows 0..63 / 64..127
    const uint32_t soff0 = (uint32_t)(r0 * (ROWP * 2) + cc * 16);
    const uint32_t soff1 = (uint32_t)((r0 + 64) * (ROWP * 2) + cc * 16);

    auto load_stage = [&](int st, int k0) {
        uint32_t base = sb + st * STAGE_BYTES;
        const size_t g0 = (size_t)r0 * K + k0 + cc * 8;
        const size_t g1 = (size_t)(r0 + 64) * K + k0 + cc * 8;
        CP_ASYNC16(base + soff0,                  src0 + g0);
        CP_ASYNC16(base + soff1,                  src0 + g1);
        CP_ASYNC16(base + TILE_BYTES + soff0,     src1 + g0);
        CP_ASYNC16(base + TILE_BYTES + soff1,     src1 + g1);
        CP_ASYNC16(base + 2 * TILE_BYTES + soff0, src2 + g0);
        CP_ASYNC16(base + 2 * TILE_BYTES + soff1, src2 + g1);
        CP_ASYNC16(base + 3 * TILE_BYTES + soff0, src3 + g0);
        CP_ASYNC16(base + 3 * TILE_BYTES + soff1, src3 + g1);
    };

    float c[4][4][4];
    #pragma unroll
    for (int i = 0; i < 4; i++)
        #pragma unroll
        for (int j = 0; j < 4; j++)
            #pragma unroll
            for (int q = 0; q < 4; q++) c[i][j][q] = 0.f;

    // ldmatrix lane addressing
    const int a_row = wm * 64 + (lane & 15);
    const int a_kad = (lane >> 4) << 3;
    const int b_row = wn * 32 + (lane & 7) + ((lane & 16) >> 1);
    const int b_kad = (lane & 8);

    const int nc = K >> 5;
    load_stage(0, 0);
    CP_COMMIT();

    for (int ci = 0; ci < nc; ci++) {
        if (ci + 1 < nc) {
            load_stage((ci + 1) & 1, (ci + 1) << 5);
            CP_COMMIT();
            CP_WAIT(1);
        } else {
            CP_WAIT(0);
        }
        __syncthreads();

        const uint32_t base = sb + (ci & 1) * STAGE_BYTES;
        const uint32_t aH = base, aL = base + TILE_BYTES;
        const uint32_t bH = base + 2 * TILE_BYTES, bL = base + 3 * TILE_BYTES;

        #pragma unroll
        for (int kk = 0; kk < 32; kk += 16) {
            uint32_t ah[4][4], bh[2][4], bl[2][4];
            const uint32_t akoff = (uint32_t)((kk + a_kad) * 2);
            const uint32_t bkoff = (uint32_t)((kk + b_kad) * 2);
            #pragma unroll
            for (int mi = 0; mi < 4; mi++)
                LDSM_X4(ah[mi], aH + (a_row + mi * 16) * (ROWP * 2) + akoff);
            #pragma unroll
            for (int nj = 0; nj < 2; nj++) {
                LDSM_X4(bh[nj], bH + (b_row + nj * 16) * (ROWP * 2) + bkoff);
                LDSM_X4(bl[nj], bL + (b_row + nj * 16) * (ROWP * 2) + bkoff);
            }
            // pass 1: Ahi * Bhi ; pass 2: Ahi * Blo
            #pragma unroll
            for (int mi = 0; mi < 4; mi++)
                #pragma unroll
                for (int ni = 0; ni < 4; ni++) {
                    MMA_BF16(c[mi][ni], ah[mi],
                             bh[ni >> 1][(ni & 1) * 2], bh[ni >> 1][(ni & 1) * 2 + 1]);
                    MMA_BF16(c[mi][ni], ah[mi],
                             bl[ni >> 1][(ni & 1) * 2], bl[ni >> 1][(ni & 1) * 2 + 1]);
                }
            // pass 3: Alo * Bhi (reuse ah registers)
            uint32_t al[4][4];
            #pragma unroll
            for (int mi = 0; mi < 4; mi++)
                LDSM_X4(al[mi], aL + (a_row + mi * 16) * (ROWP * 2) + akoff);
            #pragma unroll
            for (int mi = 0; mi < 4; mi++)
                #pragma unroll
                for (int ni = 0; ni < 4; ni++)
                    MMA_BF16(c[mi][ni], al[mi],
                             bh[ni >> 1][(ni & 1) * 2], bh[ni >> 1][(ni & 1) * 2 + 1]);
        }
        __syncthreads();
    }

    // epilogue
    const int er = m0 + wm * 64 + (lane >> 2);
    const int ec = n0 + wn * 32 + (lane & 3) * 2;
    #pragma unroll
    for (int mi = 0; mi < 4; mi++) {
        #pragma unroll
        for (int ni = 0; ni < 4; ni++) {
            int row = er + mi * 16;
            int col = ec + ni * 8;
            float2 v0 = make_float2(c[mi][ni][0], c[mi][ni][1]);
            float2 v1 = make_float2(c[mi][ni][2], c[mi][ni][3]);
            if (R) {
                float2 t0 = *(const float2*)(R + (size_t)row * N + col);
                float2 t1 = *(const float2*)(R + (size_t)(row + 8) * N + col);
                v0.x += t0.x; v0.y += t0.y;
                v1.x += t1.x; v1.y += t1.y;
            }
            *(float2*)(C + (size_t)row * N + col) = v0;
            *(float2*)(C + (size_t)(row + 8) * N + col) = v1;
        }
    }
}

// ---------------------------------------------------------------------------
// RoPE (duplicated-half): in-place on Q and K (fp32)
// ---------------------------------------------------------------------------
__global__ __launch_bounds__(256) void rope_kernel(
    float* __restrict__ Q, float* __restrict__ Kp,
    const float* __restrict__ cosb, const float* __restrict__ sinb)
{
    int idx = blockIdx.x * blockDim.x + threadIdx.x;
    int d = idx & 63;
    int h = (idx >> 6) & (H - 1);
    int s = idx >> 10;
    size_t base = (size_t)s * D + (size_t)h * HD;
    float c = cosb[s * HD + d];
    float sn = sinb[s * HD + d];

    float q0 = Q[base + d], q1 = Q[base + d + 64];
    Q[base + d]      = q0 * c - q1 * sn;
    Q[base + d + 64] = q1 * c + q0 * sn;

    float k0 = Kp[base + d], k1 = Kp[base + d + 64];
    Kp[base + d]      = k0 * c - k1 * sn;
    Kp[base + d + 64] = k1 * c + k0 * sn;
}

// ---------------------------------------------------------------------------
// Causal attention: block = (head, 16 queries), K/V staged in SMEM tiles of 32
// keys shared by all 16 query-warps. Warp per query, online softmax, fp32.
// ---------------------------------------------------------------------------
#define AQ 16
__global__ __launch_bounds__(512) void attn_kernel(
    const float* __restrict__ Q, const float* __restrict__ K,
    const float* __restrict__ V, float* __restrict__ O)
{
    __shared__ float sK[32][128];
    __shared__ float sV[32][128];

    const int tid = threadIdx.x;
    const int warp = tid >> 5, lane = tid & 31;
    const int qr = blockIdx.x * AQ + warp;
    const int h = blockIdx.y;
    const int qmax = blockIdx.x * AQ + AQ - 1;
    const size_t hbase = (size_t)h * HD;
    const size_t hoff = hbase + (size_t)lane * 4;

    float4 q4 = *(const float4*)(Q + (size_t)qr * D + hoff);
    float m = -1e30f, l = 0.f;
    float ax = 0.f, ay = 0.f, az = 0.f, aw = 0.f;
    const float scale = 0.08838834764831845f;

    for (int t0 = 0; t0 <= qmax; t0 += 32) {
        __syncthreads();
        // cooperative tile load: 32 keys x 128 floats for K and V
        #pragma unroll
        for (int i = 0; i < 2; i++) {
            int el = tid + i * 512;        // 0..1023 float4 slots
            int row = el >> 5;
            int c4 = (el & 31) * 4;
            int gr = t0 + row;
            if (gr < S) {
                *(float4*)(&sK[row][c4]) = *(const float4*)(K + (size_t)gr * D + hbase + c4);
                *(float4*)(&sV[row][c4]) = *(const float4*)(V + (size_t)gr * D + hbase + c4);
            }
        }
        __syncthreads();

        int krel = qr - t0;
        if (krel < 0) continue;
        int kend = krel < 31 ? krel : 31;
        for (int kk = 0; kk <= kend; kk++) {
            float4 k4 = *(const float4*)(&sK[kk][lane * 4]);
            float s = q4.x * k4.x + q4.y * k4.y + q4.z * k4.z + q4.w * k4.w;
            #pragma unroll
            for (int o = 16; o; o >>= 1) s += __shfl_xor_sync(0xffffffffu, s, o);
            s *= scale;
            float nm = fmaxf(m, s);
            float f = __expf(m - nm);
            float p = __expf(s - nm);
            float4 v4 = *(const float4*)(&sV[kk][lane * 4]);
            l = l * f + p;
            ax = ax * f + p * v4.x;
            ay = ay * f + p * v4.y;
            az = az * f + p * v4.z;
            aw = aw * f + p * v4.w;
            m = nm;
        }
    }
    float rl = 1.f / l;
    *(float4*)(O + (size_t)qr * D + hoff) = make_float4(ax * rl, ay * rl, az * rl, aw * rl);
}

// ---------------------------------------------------------------------------
// Launch
// ---------------------------------------------------------------------------
extern "C" void kernel_launch(void* const* d_in, const int* in_sizes, int n_in,
                              void* d_out, int out_size)
{
    const float* x    = (const float*)d_in[0];
    const float* fcos = (const float*)d_in[2];
    const float* fsin = (const float*)d_in[3];
    const float* wq   = (const float*)d_in[4];
    const float* wk   = (const float*)d_in[5];
    const float* wv   = (const float*)d_in[6];
    const float* wo   = (const float*)d_in[7];
    const float* w1   = (const float*)d_in[8];
    const float* w2   = (const float*)d_in[9];
    const float* w3   = (const float*)d_in[10];
    const float* anw  = (const float*)d_in[11];
    const float* fnw  = (const float*)d_in[12];
    float* out = (float*)d_out;

    float *q, *k, *v, *ao, *x1, *h1, *h3;
    __nv_bfloat16 *nxh, *nxl, *aoh, *aol, *gh, *gl;
    __nv_bfloat16 *wqh, *wql, *wkh, *wkl, *wvh, *wvl, *woh, *wol;
    __nv_bfloat16 *w1h, *w1l, *w3h, *w3l, *w2h, *w2l;

    cudaGetSymbolAddress((void**)&q, g_q);
    cudaGetSymbolAddress((void**)&k, g_k);
    cudaGetSymbolAddress((void**)&v, g_v);
    cudaGetSymbolAddress((void**)&ao, g_ao);
    cudaGetSymbolAddress((void**)&x1, g_x1);
    cudaGetSymbolAddress((void**)&h1, g_h1);
    cudaGetSymbolAddress((void**)&h3, g_h3);
    cudaGetSymbolAddress((void**)&nxh, g_nx_hi);
    cudaGetSymbolAddress((void**)&nxl, g_nx_lo);
    cudaGetSymbolAddress((void**)&aoh, g_ao_hi);
    cudaGetSymbolAddress((void**)&aol, g_ao_lo);
    cudaGetSymbolAddress((void**)&gh, g_g_hi);
    cudaGetSymbolAddress((void**)&gl, g_g_lo);
    cudaGetSymbolAddress((void**)&wqh, g_wqT_hi);
    cudaGetSymbolAddress((void**)&wql, g_wqT_lo);
    cudaGetSymbolAddress((void**)&wkh, g_wkT_hi);
    cudaGetSymbolAddress((void**)&wkl, g_wkT_lo);
    cudaGetSymbolAddress((void**)&wvh, g_wvT_hi);
    cudaGetSymbolAddress((void**)&wvl, g_wvT_lo);
    cudaGetSymbolAddress((void**)&woh, g_woT_hi);
    cudaGetSymbolAddress((void**)&wol, g_woT_lo);
    cudaGetSymbolAddress((void**)&w1h, g_w1T_hi);
    cudaGetSymbolAddress((void**)&w1l, g_w1T_lo);
    cudaGetSymbolAddress((void**)&w3h, g_w3T_hi);
    cudaGetSymbolAddress((void**)&w3l, g_w3T_lo);
    cudaGetSymbolAddress((void**)&w2h, g_w2T_hi);
    cudaGetSymbolAddress((void**)&w2l, g_w2T_lo);

    cudaFuncSetAttribute(gemm3_kernel, cudaFuncAttributeMaxDynamicSharedMemorySize,
                         GEMM_SMEM);

    dim3 tb(32, 8);
    transpose_split_kernel<<<dim3(D / 32, D / 32), tb>>>(wq, wqh, wql, D, D);
    transpose_split_kernel<<<dim3(D / 32, D / 32), tb>>>(wk, wkh, wkl, D, D);
    transpose_split_kernel<<<dim3(D / 32, D / 32), tb>>>(wv, wvh, wvl, D, D);
    transpose_split_kernel<<<dim3(D / 32, D / 32), tb>>>(wo, woh, wol, D, D);
    transpose_split_kernel<<<dim3(FFI / 32, D / 32), tb>>>(w1, w1h, w1l, D, FFI);
    transpose_split_kernel<<<dim3(FFI / 32, D / 32), tb>>>(w3, w3h, w3l, D, FFI);
    transpose_split_kernel<<<dim3(D / 32, FFI / 32), tb>>>(w2, w2h, w2l, FFI, D);

    dim3 gDD(D / 128, S / 128);
    dim3 gDI(FFI / 128, S / 128);

    // attention sub-block
    rmsnorm_split_kernel<<<S, 256>>>(x, anw, nxh, nxl);
    gemm3_kernel<<<gDD, 256, GEMM_SMEM>>>(nxh, nxl, wqh, wql, nullptr, q, D, D);
    gemm3_kernel<<<gDD, 256, GEMM_SMEM>>>(nxh, nxl, wkh, wkl, nullptr, k, D, D);
    gemm3_kernel<<<gDD, 256, GEMM_SMEM>>>(nxh, nxl, wvh, wvl, nullptr, v, D, D);
    rope_kernel<<<(S * H * 64) / 256, 256>>>(q, k, fcos, fsin);
    attn_kernel<<<dim3(S / AQ, H), 512>>>(q, k, v, ao);
    split_kernel<<<(S * D / 4) / 256, 256>>>(ao, aoh, aol);
    gemm3_kernel<<<gDD, 256, GEMM_SMEM>>>(aoh, aol, woh, wol, x, x1, D, D);

    // ffn sub-block
    rmsnorm_split_kernel<<<S, 256>>>(x1, fnw, nxh, nxl);
    gemm3_kernel<<<gDI, 256, GEMM_SMEM>>>(nxh, nxl, w1h, w1l, nullptr, h1, FFI, D);
    gemm3_kernel<<<gDI, 256, GEMM_SMEM>>>(nxh, nxl, w3h, w3l, nullptr, h3, FFI, D);
    silu_mul_split_kernel<<<((size_t)S * FFI / 4) / 256, 256>>>(h1, h3, gh, gl);
    gemm3_kernel<<<gDD, 256, GEMM_SMEM>>>(gh, gl, w2h, w2l, x1, out, D, FFI);
}